// round 16
// baseline (speedup 1.0000x reference)
#include <cuda_runtime.h>
#include <math.h>
#include <float.h>

#define NP     125
#define NC     21
#define NBATCH 16384
#define WPB    8              // warps (batch items) per block
#define NT     (WPB * 32)
#define THRESH 0.3f

// per-item partials: [comp][item], comp: 0=loc 1=ang 2=confpos 3=hard 4=npos
__device__ float g_part[5 * NBATCH];

__device__ __forceinline__ float warp_sum_f(float v) {
    #pragma unroll
    for (int o = 16; o; o >>= 1) v += __shfl_xor_sync(0xffffffffu, v, o);
    return v;
}
__device__ __forceinline__ int warp_sum_i(int v) {
    #pragma unroll
    for (int o = 16; o; o >>= 1) v += __shfl_xor_sync(0xffffffffu, v, o);
    return v;
}
__device__ __forceinline__ double warp_sum_d(double v) {
    #pragma unroll
    for (int o = 16; o; o >>= 1) v += __shfl_xor_sync(0xffffffffu, v, o);
    return v;
}

__global__ __launch_bounds__(NT) void mbloss_main_kernel(
    const float* __restrict__ locs,     // [B, NP, 6]
    const float* __restrict__ scores,   // [B, NP, NC]
    const float* __restrict__ target,   // [B, 1, 8]
    const float* __restrict__ priors)   // [NP, 4]
{
    const int w    = threadIdx.x >> 5;
    const int lane = threadIdx.x & 31;
    const int b    = blockIdx.x * WPB + w;

    // ---- target (uniform per warp, L1/L2 broadcast) ----
    const float* tg = target + (size_t)b * 8;
    const float bcx  = __ldg(tg + 0), bcy  = __ldg(tg + 1);
    const float bw   = __ldg(tg + 2), bh   = __ldg(tg + 3);
    const float tsin = __ldg(tg + 5), tcos = __ldg(tg + 6);
    const int   lab  = (int)__ldg(tg + 7);

    // ---- IoU for this lane's 4 priors (p = c*32 + lane) ----
    float iou[4], pxc[4], pyc[4], pwv[4], phv[4];
    #pragma unroll
    for (int c = 0; c < 4; c++) {
        const int p = c * 32 + lane;
        if (p < NP) {
            const float4 pr = __ldg((const float4*)(priors) + p);
            pxc[c] = pr.x; pyc[c] = pr.y; pwv[c] = pr.z; phv[c] = pr.w;
            const float iw = fmaxf(0.0f, fminf(bcx + bw * 0.5f, pr.x + pr.z * 0.5f)
                                        - fmaxf(bcx - bw * 0.5f, pr.x - pr.z * 0.5f));
            const float ih = fmaxf(0.0f, fminf(bcy + bh * 0.5f, pr.y + pr.w * 0.5f)
                                        - fmaxf(bcy - bh * 0.5f, pr.y - pr.w * 0.5f));
            const float inter = iw * ih;
            iou[c] = inter / (bw * bh + pr.z * pr.w - inter);
        } else {
            iou[c] = -1.0f;
            pxc[c] = pyc[c] = pwv[c] = phv[c] = 1.0f;
        }
    }

    // ---- argmax with first-index tiebreak (matches jnp.argmax) ----
    float bv = iou[0]; int bi = lane;          // in-lane indices increase with c
    #pragma unroll
    for (int c = 1; c < 4; c++) {
        const int idx = c * 32 + lane;
        if (iou[c] > bv) { bv = iou[c]; bi = idx; }
    }
    #pragma unroll
    for (int o = 16; o; o >>= 1) {
        const float ov = __shfl_xor_sync(0xffffffffu, bv, o);
        const int   oi = __shfl_xor_sync(0xffffffffu, bi, o);
        if (ov > bv || (ov == bv && oi < bi)) { bv = ov; bi = oi; }
    }

    // ---- per-prior losses (warp-local, no barriers) ----
    const float* srow = scores + (size_t)b * (NP * NC);
    const float* lrow = locs   + (size_t)b * (NP * 6);

    float v[4];                // sort values (conf_neg; 0 for positives)
    float loc_c = 0.0f, ang_c = 0.0f, cp_c = 0.0f;
    int   np_c = 0;

    #pragma unroll
    for (int c = 0; c < 4; c++) {
        const int p = c * 32 + lane;
        float sv = -FLT_MAX;
        if (p < NP) {
            const float ov  = (p == bi) ? 1.0f : iou[c];
            const bool  pos = !(ov < THRESH);

            // logsumexp (scores ~ N(0,1): direct sum-exp is safe and exact enough)
            const float* sr = srow + p * NC;
            float se = 0.0f;
            #pragma unroll
            for (int j = 0; j < NC; j++) se += __expf(__ldg(sr + j));
            const float lse  = __logf(se);
            const int   cls  = pos ? lab : 0;
            const float conf = lse - __ldg(sr + cls);

            if (pos) {
                np_c++;
                cp_c += conf;
                sv = 0.0f;                       // positives sort as 0.0 (reference semantics)
                const float* lr = lrow + p * 6;
                const float g0 = (bcx - pxc[c]) * 10.0f / pwv[c];
                const float g1 = (bcy - pyc[c]) * 10.0f / phv[c];
                const float g2 = __logf(bw / pwv[c]) * 5.0f;
                const float g3 = __logf(bh / phv[c]) * 5.0f;
                const float g[4] = {g0, g1, g2, g3};
                #pragma unroll
                for (int k = 0; k < 4; k++) {
                    const float d  = __ldg(lr + k) - g[k];
                    const float ad = fabsf(d);
                    loc_c += (ad < 1.0f) ? 0.5f * d * d : ad - 0.5f;
                }
                const float da0 = __ldg(lr + 4) - tsin;
                const float da1 = __ldg(lr + 5) - tcos;
                ang_c += da0 * da0 + da1 * da1;
            } else {
                sv = conf;
            }
        }
        v[c] = sv;
    }

    const int npos = warp_sum_i(np_c);

    // ---- in-register 128-wide bitonic sort (descending), 4 values/lane ----
    // virtual index vi = lane*4 + r; distance >= 4 => shfl_xor, distance 1,2 => in-register
    const int vbase = lane * 4;
    #pragma unroll
    for (int k = 2; k <= 128; k <<= 1) {
        #pragma unroll
        for (int j = k >> 1; j > 0; j >>= 1) {
            if (j >= 4) {
                const int src = j >> 2;
                #pragma unroll
                for (int r = 0; r < 4; r++) {
                    const float other = __shfl_xor_sync(0xffffffffu, v[r], src);
                    const int  vi    = vbase + r;
                    const bool lower = ((vi & j) == 0);
                    const bool desc  = ((vi & k) == 0);
                    v[r] = (lower == desc) ? fmaxf(v[r], other) : fminf(v[r], other);
                }
            } else {
                #pragma unroll
                for (int r = 0; r < 4; r++) {
                    if ((r & j) == 0) {
                        const int  vi   = vbase + r;
                        const bool desc = ((vi & k) == 0);
                        const float a  = v[r], c2 = v[r | j];
                        const float mx = fmaxf(a, c2), mn = fminf(a, c2);
                        v[r]     = desc ? mx : mn;
                        v[r | j] = desc ? mn : mx;
                    }
                }
            }
        }
    }

    // ---- hard-negative sum: ranks < min(3*npos, NP) ----
    int K = 3 * npos;
    if (K > NP) K = NP;
    float hard_c = 0.0f;
    #pragma unroll
    for (int r = 0; r < 4; r++)
        if (vbase + r < K) hard_c += v[r];

    // ---- warp reductions -> per-item partials (plain stores, no atomics/fences) ----
    const float wl = warp_sum_f(loc_c);
    const float wa = warp_sum_f(ang_c);
    const float wc = warp_sum_f(cp_c);
    const float wh = warp_sum_f(hard_c);
    if (lane == 0) {
        g_part[0 * NBATCH + b] = wl;
        g_part[1 * NBATCH + b] = wa;
        g_part[2 * NBATCH + b] = wc;
        g_part[3 * NBATCH + b] = wh;
        g_part[4 * NBATCH + b] = (float)npos;
    }
}

#define FT 1024
__global__ __launch_bounds__(FT) void finalize_kernel(float* __restrict__ out) {
    __shared__ double s_d[FT / 32];
    __shared__ double s_comp[5];

    const int w    = threadIdx.x >> 5;
    const int lane = threadIdx.x & 31;

    #pragma unroll
    for (int cidx = 0; cidx < 5; cidx++) {
        const float* base = g_part + cidx * NBATCH;
        double s = 0.0;
        for (int i = threadIdx.x; i < NBATCH; i += FT) s += (double)base[i];
        s = warp_sum_d(s);
        if (lane == 0) s_d[w] = s;
        __syncthreads();
        if (threadIdx.x == 0) {
            double t = 0.0;
            #pragma unroll
            for (int i = 0; i < FT / 32; i++) t += s_d[i];
            s_comp[cidx] = t;
        }
        __syncthreads();
    }

    if (threadIdx.x == 0) {
        const double npos = s_comp[4];
        const double conf = (s_comp[3] + s_comp[2]) / npos;
        const double loc  = s_comp[0] / (npos * 4.0);
        const double ang  = 25.0 * s_comp[1] / (npos * 2.0);
        out[0] = (float)conf;
        out[1] = (float)loc;
        out[2] = (float)ang;
        out[3] = (float)(conf + loc + ang);
    }
}

extern "C" void kernel_launch(void* const* d_in, const int* in_sizes, int n_in,
                              void* d_out, int out_size) {
    const float* locs   = (const float*)d_in[0];  // predicted_locs
    const float* scores = (const float*)d_in[1];  // predicted_scores
    const float* target = (const float*)d_in[2];  // target
    const float* priors = (const float*)d_in[3];  // priors_cxcy
    float* out = (float*)d_out;

    mbloss_main_kernel<<<NBATCH / WPB, NT>>>(locs, scores, target, priors);
    finalize_kernel<<<1, FT>>>(out);
}

// round 17
// speedup vs baseline: 2.1429x; 2.1429x over previous
#include <cuda_runtime.h>
#include <math.h>
#include <float.h>

#define NP     125
#define NC     21
#define NBATCH 16384
#define WPB    8              // warps (batch items) per block
#define NT     (WPB * 32)
#define THRESH 0.3f

// [0]=loc_sum, [1]=angle_sum, [2]=conf_pos_sum, [3]=hard_neg_sum, [4]=n_pos_total
// Zero at module load; finalize_kernel resets to zero after each run, so every
// graph replay starts from a clean accumulator (no separate zeroing launch).
__device__ double g_acc[5];

__device__ __forceinline__ float warp_sum_f(float v) {
    #pragma unroll
    for (int o = 16; o; o >>= 1) v += __shfl_xor_sync(0xffffffffu, v, o);
    return v;
}
__device__ __forceinline__ int warp_sum_i(int v) {
    #pragma unroll
    for (int o = 16; o; o >>= 1) v += __shfl_xor_sync(0xffffffffu, v, o);
    return v;
}

__global__ __launch_bounds__(NT) void mbloss_main_kernel(
    const float* __restrict__ locs,     // [B, NP, 6]
    const float* __restrict__ scores,   // [B, NP, NC]
    const float* __restrict__ target,   // [B, 1, 8]
    const float* __restrict__ priors)   // [NP, 4]
{
    __shared__ float s_loc[WPB], s_ang[WPB], s_cp[WPB], s_hard[WPB];
    __shared__ int   s_np[WPB];

    const int w    = threadIdx.x >> 5;
    const int lane = threadIdx.x & 31;
    const int b    = blockIdx.x * WPB + w;

    // ---- target (uniform per warp, L1/L2 broadcast) ----
    const float* tg = target + (size_t)b * 8;
    const float bcx  = __ldg(tg + 0), bcy  = __ldg(tg + 1);
    const float bw   = __ldg(tg + 2), bh   = __ldg(tg + 3);
    const float tsin = __ldg(tg + 5), tcos = __ldg(tg + 6);
    const int   lab  = (int)__ldg(tg + 7);

    // ---- IoU for this lane's 4 priors (p = c*32 + lane) ----
    float iou[4], pxc[4], pyc[4], pwv[4], phv[4];
    #pragma unroll
    for (int c = 0; c < 4; c++) {
        const int p = c * 32 + lane;
        if (p < NP) {
            const float4 pr = __ldg((const float4*)(priors) + p);
            pxc[c] = pr.x; pyc[c] = pr.y; pwv[c] = pr.z; phv[c] = pr.w;
            const float iw = fmaxf(0.0f, fminf(bcx + bw * 0.5f, pr.x + pr.z * 0.5f)
                                        - fmaxf(bcx - bw * 0.5f, pr.x - pr.z * 0.5f));
            const float ih = fmaxf(0.0f, fminf(bcy + bh * 0.5f, pr.y + pr.w * 0.5f)
                                        - fmaxf(bcy - bh * 0.5f, pr.y - pr.w * 0.5f));
            const float inter = iw * ih;
            iou[c] = inter / (bw * bh + pr.z * pr.w - inter);
        } else {
            iou[c] = -1.0f;
            pxc[c] = pyc[c] = pwv[c] = phv[c] = 1.0f;
        }
    }

    // ---- argmax with first-index tiebreak (matches jnp.argmax) ----
    float bv = iou[0]; int bi = lane;          // in-lane indices increase with c
    #pragma unroll
    for (int c = 1; c < 4; c++) {
        const int idx = c * 32 + lane;
        if (iou[c] > bv) { bv = iou[c]; bi = idx; }
    }
    #pragma unroll
    for (int o = 16; o; o >>= 1) {
        const float ov = __shfl_xor_sync(0xffffffffu, bv, o);
        const int   oi = __shfl_xor_sync(0xffffffffu, bi, o);
        if (ov > bv || (ov == bv && oi < bi)) { bv = ov; bi = oi; }
    }

    // ---- per-prior losses (warp-local, no barriers) ----
    const float* srow = scores + (size_t)b * (NP * NC);
    const float* lrow = locs   + (size_t)b * (NP * 6);

    float v[4];                // sort values (conf_neg; 0 for positives)
    float loc_c = 0.0f, ang_c = 0.0f, cp_c = 0.0f;
    int   np_c = 0;

    #pragma unroll
    for (int c = 0; c < 4; c++) {
        const int p = c * 32 + lane;
        float sv = -FLT_MAX;
        if (p < NP) {
            const float ov  = (p == bi) ? 1.0f : iou[c];
            const bool  pos = !(ov < THRESH);

            // logsumexp (scores ~ N(0,1): direct sum-exp is safe and exact enough)
            const float* sr = srow + p * NC;
            float se = 0.0f;
            #pragma unroll
            for (int j = 0; j < NC; j++) se += __expf(__ldg(sr + j));
            const float lse  = __logf(se);
            const int   cls  = pos ? lab : 0;
            const float conf = lse - __ldg(sr + cls);

            if (pos) {
                np_c++;
                cp_c += conf;
                sv = 0.0f;                       // positives sort as 0.0 (reference semantics)
                const float* lr = lrow + p * 6;
                const float g0 = (bcx - pxc[c]) * 10.0f / pwv[c];
                const float g1 = (bcy - pyc[c]) * 10.0f / phv[c];
                const float g2 = __logf(bw / pwv[c]) * 5.0f;
                const float g3 = __logf(bh / phv[c]) * 5.0f;
                const float g[4] = {g0, g1, g2, g3};
                #pragma unroll
                for (int k = 0; k < 4; k++) {
                    const float d  = __ldg(lr + k) - g[k];
                    const float ad = fabsf(d);
                    loc_c += (ad < 1.0f) ? 0.5f * d * d : ad - 0.5f;
                }
                const float da0 = __ldg(lr + 4) - tsin;
                const float da1 = __ldg(lr + 5) - tcos;
                ang_c += da0 * da0 + da1 * da1;
            } else {
                sv = conf;
            }
        }
        v[c] = sv;
    }

    const int npos = warp_sum_i(np_c);

    // ---- in-register 128-wide bitonic sort (descending), 4 values/lane ----
    // virtual index vi = lane*4 + r; distance >= 4 => shfl_xor, distance 1,2 => in-register
    const int vbase = lane * 4;
    #pragma unroll
    for (int k = 2; k <= 128; k <<= 1) {
        #pragma unroll
        for (int j = k >> 1; j > 0; j >>= 1) {
            if (j >= 4) {
                const int src = j >> 2;
                #pragma unroll
                for (int r = 0; r < 4; r++) {
                    const float other = __shfl_xor_sync(0xffffffffu, v[r], src);
                    const int  vi    = vbase + r;
                    const bool lower = ((vi & j) == 0);
                    const bool desc  = ((vi & k) == 0);
                    v[r] = (lower == desc) ? fmaxf(v[r], other) : fminf(v[r], other);
                }
            } else {
                #pragma unroll
                for (int r = 0; r < 4; r++) {
                    if ((r & j) == 0) {
                        const int  vi   = vbase + r;
                        const bool desc = ((vi & k) == 0);
                        const float a  = v[r], c2 = v[r | j];
                        const float mx = fmaxf(a, c2), mn = fminf(a, c2);
                        v[r]     = desc ? mx : mn;
                        v[r | j] = desc ? mn : mx;
                    }
                }
            }
        }
    }

    // ---- hard-negative sum: ranks < min(3*npos, NP) ----
    int K = 3 * npos;
    if (K > NP) K = NP;
    float hard_c = 0.0f;
    #pragma unroll
    for (int r = 0; r < 4; r++)
        if (vbase + r < K) hard_c += v[r];

    // ---- warp reductions, then one block-level aggregation ----
    const float wl = warp_sum_f(loc_c);
    const float wa = warp_sum_f(ang_c);
    const float wc = warp_sum_f(cp_c);
    const float wh = warp_sum_f(hard_c);
    if (lane == 0) {
        s_loc[w] = wl; s_ang[w] = wa; s_cp[w] = wc; s_hard[w] = wh; s_np[w] = npos;
    }
    __syncthreads();

    if (threadIdx.x == 0) {
        float tl = 0.f, ta = 0.f, tc = 0.f, th = 0.f; int tn = 0;
        #pragma unroll
        for (int i = 0; i < WPB; i++) {
            tl += s_loc[i]; ta += s_ang[i]; tc += s_cp[i]; th += s_hard[i]; tn += s_np[i];
        }
        atomicAdd(&g_acc[0], (double)tl);
        atomicAdd(&g_acc[1], (double)ta);
        atomicAdd(&g_acc[2], (double)tc);
        atomicAdd(&g_acc[3], (double)th);
        atomicAdd(&g_acc[4], (double)tn);
    }
}

__global__ void finalize_kernel(float* __restrict__ out) {
    if (threadIdx.x == 0) {
        const double npos = g_acc[4];
        const double conf = (g_acc[3] + g_acc[2]) / npos;
        const double loc  = g_acc[0] / (npos * 4.0);
        const double ang  = 25.0 * g_acc[1] / (npos * 2.0);
        out[0] = (float)conf;
        out[1] = (float)loc;
        out[2] = (float)ang;
        out[3] = (float)(conf + loc + ang);
        // self-reset: next run (or graph replay) starts from zeroed accumulators
        g_acc[0] = 0.0; g_acc[1] = 0.0; g_acc[2] = 0.0; g_acc[3] = 0.0; g_acc[4] = 0.0;
    }
}

extern "C" void kernel_launch(void* const* d_in, const int* in_sizes, int n_in,
                              void* d_out, int out_size) {
    const float* locs   = (const float*)d_in[0];  // predicted_locs
    const float* scores = (const float*)d_in[1];  // predicted_scores
    const float* target = (const float*)d_in[2];  // target
    const float* priors = (const float*)d_in[3];  // priors_cxcy
    float* out = (float*)d_out;

    mbloss_main_kernel<<<NBATCH / WPB, NT>>>(locs, scores, target, priors);
    finalize_kernel<<<1, 32>>>(out);
}